// round 16
// baseline (speedup 1.0000x reference)
#include <cuda_runtime.h>

#define D_MODEL 256
#define CH_TILE 32
#define QUADS 4                         // position-quads per thread per channel
#define WARP_POS (32 * 4 * QUADS)       // 512 positions per warp
#define BLOCK_WARPS 8
#define BLOCK_POS (WARP_POS * BLOCK_WARPS)  // 4096 positions per block

// Collapsed conv per stream: zero-fill upsample + conv + strided gather reduces to
// a small FIR on the original samples (stream0: 1 tap, stream1: 3 taps, stream2: 5 taps).
template <int SID, bool GUARDED>
__device__ __forceinline__ void run_compute(
    const float* __restrict__ x, const float* __restrict__ W,
    const float* __restrict__ b, float* __restrict__ out,
    int l, int ML)
{
    const int warp = threadIdx.x >> 5;
    const int lane = threadIdx.x & 31;
    const int warpBase = blockIdx.x * BLOCK_POS + warp * WARP_POS;

    // Input windows loaded ONCE per thread; reused across the 32-channel tile.
    // Window q covers x[pq-4 .. pq+7] (12 floats, 3 float4s).
    float xs[QUADS * 12];
    #pragma unroll
    for (int q = 0; q < QUADS; q++) {
        const int pq = warpBase + q * 128 + lane * 4;
        #pragma unroll
        for (int j = 0; j < 3; j++) {
            const int bb = pq - 4 + j * 4;
            float4 t;
            if (!GUARDED) {
                t = *reinterpret_cast<const float4*>(x + bb);
            } else if (bb >= 0 && bb + 4 <= l) {
                t = *reinterpret_cast<const float4*>(x + bb);
            } else {
                t.x = (bb     >= 0 && bb     < l) ? x[bb]     : 0.0f;
                t.y = (bb + 1 >= 0 && bb + 1 < l) ? x[bb + 1] : 0.0f;
                t.z = (bb + 2 >= 0 && bb + 2 < l) ? x[bb + 2] : 0.0f;
                t.w = (bb + 3 >= 0 && bb + 3 < l) ? x[bb + 3] : 0.0f;
            }
            xs[q * 12 + j * 4 + 0] = t.x;
            xs[q * 12 + j * 4 + 1] = t.y;
            xs[q * 12 + j * 4 + 2] = t.z;
            xs[q * 12 + j * 4 + 3] = t.w;
        }
    }

    const int ch0 = blockIdx.y * CH_TILE;
    #pragma unroll 1
    for (int c = 0; c < CH_TILE; c++) {
        const int ch = ch0 + c;
        const float bias = __ldg(&b[ch]);
        const float* Wc = W + ch * 5;
        float w0 = 0.f, w1 = 0.f, w2, w3 = 0.f, w4 = 0.f;
        w2 = __ldg(&Wc[2]);
        if (SID >= 1) { w0 = __ldg(&Wc[0]); w4 = __ldg(&Wc[4]); }
        if (SID == 2) { w1 = __ldg(&Wc[1]); w3 = __ldg(&Wc[3]); }

        float* rowOut = out + ((size_t)(SID * D_MODEL + ch)) * (size_t)ML;

        #pragma unroll
        for (int q = 0; q < QUADS; q++) {
            const int pq = warpBase + q * 128 + lane * 4;
            if (GUARDED && pq >= ML) continue;

            float v[4];
            #pragma unroll
            for (int i = 0; i < 4; i++) {
                // xs index: x[pq + k] == xs[q*12 + 4 + k]
                float val;
                if (SID == 0) {
                    val = fmaf(w2, xs[q * 12 + 4 + i], bias);
                } else if (SID == 1) {
                    val = fmaf(w0, xs[q * 12 + 3 + i],
                          fmaf(w2, xs[q * 12 + 4 + i],
                          fmaf(w4, xs[q * 12 + 5 + i], bias)));
                } else {
                    val = fmaf(w0, xs[q * 12 + 2 + i],
                          fmaf(w1, xs[q * 12 + 3 + i],
                          fmaf(w2, xs[q * 12 + 4 + i],
                          fmaf(w3, xs[q * 12 + 5 + i],
                          fmaf(w4, xs[q * 12 + 6 + i], bias)))));
                }
                v[i] = (!GUARDED || (pq + i < l)) ? val : 0.0f;
            }

            // BLOCK_POS and ML are multiples of 4: pq<ML implies pq+4<=ML.
            *reinterpret_cast<float4*>(rowOut + pq) =
                make_float4(v[0], v[1], v[2], v[3]);
        }
    }
}

template <int SID>
__device__ __forceinline__ void run_zero(float* __restrict__ out, int ML)
{
    const int warp = threadIdx.x >> 5;
    const int lane = threadIdx.x & 31;
    const int warpBase = blockIdx.x * BLOCK_POS + warp * WARP_POS;
    const int ch0 = blockIdx.y * CH_TILE;
    const float4 z4 = make_float4(0.f, 0.f, 0.f, 0.f);

    #pragma unroll 1
    for (int c = 0; c < CH_TILE; c++) {
        float* rowOut = out + ((size_t)(SID * D_MODEL + ch0 + c)) * (size_t)ML;
        #pragma unroll
        for (int q = 0; q < QUADS; q++) {
            const int pq = warpBase + q * 128 + lane * 4;
            if (pq < ML)
                *reinterpret_cast<float4*>(rowOut + pq) = z4;
        }
    }
}

template <int SID>
__device__ __forceinline__ void run_stream(
    const float* __restrict__ x, const float* __restrict__ W,
    const float* __restrict__ b, float* __restrict__ out,
    int l, int ML)
{
    const int base = blockIdx.x * BLOCK_POS;
    if (base >= l) {
        run_zero<SID>(out, ML);
    } else if (base >= 4 && base + BLOCK_POS + 8 <= l) {
        run_compute<SID, false>(x, W, b, out, l, ML);
    } else {
        run_compute<SID, true>(x, W, b, out, l, ML);
    }
}

__global__ __launch_bounds__(256) void embed_x_kernel(
    const float* __restrict__ x0, const float* __restrict__ x1,
    const float* __restrict__ x2,
    const float* __restrict__ W, const float* __restrict__ b,
    float* __restrict__ out, int l0, int l1, int l2, int ML, int emit_s)
{
    if (blockIdx.z == 0)      run_stream<0>(x0, W, b, out, l0, ML);
    else if (blockIdx.z == 1) run_stream<1>(x1, W, b, out, l1, ML);
    else                      run_stream<2>(x2, W, b, out, l2, ML);

    // Fused S matrix: rows (first ML) then cols (next ML), ints stored exactly
    // as floats. Handled by the (y==0, z==0) block slice for its position range.
    if (emit_s && blockIdx.y == 0 && blockIdx.z == 0) {
        float* out_s = out + 3LL * D_MODEL * (long long)ML;
        const int base = blockIdx.x * BLOCK_POS;
        #pragma unroll
        for (int k = 0; k < BLOCK_POS / 256; k++) {
            const int j = base + k * 256 + threadIdx.x;
            if (j >= ML) break;
            int row, col;
            if (j < l0)                 { row = 0; col = j * 4; }
            else if (j < l0 + l1)       { row = 1; col = (j - l0) * 2; }
            else if (j < l0 + l1 + l2)  { row = 2; col = j - l0 - l1; }
            else                        { row = 0; col = 0; }
            out_s[j]      = (float)row;
            out_s[ML + j] = (float)col;
        }
    }
}

extern "C" void kernel_launch(void* const* d_in, const int* in_sizes, int n_in,
                              void* d_out, int out_size)
{
    const float* x0 = (const float*)d_in[0];  // x_250
    const float* x1 = (const float*)d_in[1];  // x_500
    const float* x2 = (const float*)d_in[2];  // x_1000
    const float* W  = (const float*)d_in[3];  // [256,1,5]
    const float* b  = (const float*)d_in[4];  // [256]

    const int l0 = in_sizes[0];
    const int l1 = in_sizes[1];
    const int l2 = in_sizes[2];
    int ML = l0;
    if (l1 > ML) ML = l1;
    if (l2 > ML) ML = l2;

    float* out = (float*)d_out;

    const long long x_elems = 3LL * D_MODEL * (long long)ML;
    const int emit_s = ((long long)out_size >= x_elems + 2LL * ML) ? 1 : 0;

    dim3 block(256, 1, 1);
    dim3 grid((ML + BLOCK_POS - 1) / BLOCK_POS, D_MODEL / CH_TILE, 3);
    embed_x_kernel<<<grid, block>>>(x0, x1, x2, W, b, out, l0, l1, l2, ML, emit_s);
}

// round 17
// speedup vs baseline: 1.7076x; 1.7076x over previous
#include <cuda_runtime.h>

#define D_MODEL 256
#define CH_TILE 16
#define QUADS 2                         // position-quads per thread per channel
#define WARP_POS (32 * 4 * QUADS)       // 256 positions per warp
#define BLOCK_WARPS 8
#define BLOCK_POS (WARP_POS * BLOCK_WARPS)  // 2048 positions per block

// Collapsed conv per stream: zero-fill upsample + conv + strided gather reduces to
// a small FIR on the original samples (stream0: 1 tap, stream1: 3 taps, stream2: 5 taps).
template <int SID, bool GUARDED>
__device__ __forceinline__ void run_compute(
    const float* __restrict__ x, const float* __restrict__ W,
    const float* __restrict__ b, float* __restrict__ out,
    int l, int ML)
{
    const int warp = threadIdx.x >> 5;
    const int lane = threadIdx.x & 31;
    const int warpBase = blockIdx.x * BLOCK_POS + warp * WARP_POS;

    // Input windows loaded ONCE per thread; reused across the 16-channel tile.
    // Window q covers x[pq-4 .. pq+7] (12 floats, 3 float4s).
    float xs[QUADS * 12];
    #pragma unroll
    for (int q = 0; q < QUADS; q++) {
        const int pq = warpBase + q * 128 + lane * 4;
        #pragma unroll
        for (int j = 0; j < 3; j++) {
            const int bb = pq - 4 + j * 4;
            float4 t;
            if (!GUARDED) {
                t = *reinterpret_cast<const float4*>(x + bb);
            } else if (bb >= 0 && bb + 4 <= l) {
                t = *reinterpret_cast<const float4*>(x + bb);
            } else {
                t.x = (bb     >= 0 && bb     < l) ? x[bb]     : 0.0f;
                t.y = (bb + 1 >= 0 && bb + 1 < l) ? x[bb + 1] : 0.0f;
                t.z = (bb + 2 >= 0 && bb + 2 < l) ? x[bb + 2] : 0.0f;
                t.w = (bb + 3 >= 0 && bb + 3 < l) ? x[bb + 3] : 0.0f;
            }
            xs[q * 12 + j * 4 + 0] = t.x;
            xs[q * 12 + j * 4 + 1] = t.y;
            xs[q * 12 + j * 4 + 2] = t.z;
            xs[q * 12 + j * 4 + 3] = t.w;
        }
    }

    const int ch0 = blockIdx.y * CH_TILE;
    #pragma unroll 1
    for (int c = 0; c < CH_TILE; c++) {
        const int ch = ch0 + c;
        const float bias = __ldg(&b[ch]);
        const float* Wc = W + ch * 5;
        float w0 = 0.f, w1 = 0.f, w2, w3 = 0.f, w4 = 0.f;
        w2 = __ldg(&Wc[2]);
        if (SID >= 1) { w0 = __ldg(&Wc[0]); w4 = __ldg(&Wc[4]); }
        if (SID == 2) { w1 = __ldg(&Wc[1]); w3 = __ldg(&Wc[3]); }

        float* rowOut = out + ((size_t)(SID * D_MODEL + ch)) * (size_t)ML;

        #pragma unroll
        for (int q = 0; q < QUADS; q++) {
            const int pq = warpBase + q * 128 + lane * 4;
            if (GUARDED && pq >= ML) continue;

            float v[4];
            #pragma unroll
            for (int i = 0; i < 4; i++) {
                // xs index: x[pq + k] == xs[q*12 + 4 + k]
                float val;
                if (SID == 0) {
                    val = fmaf(w2, xs[q * 12 + 4 + i], bias);
                } else if (SID == 1) {
                    val = fmaf(w0, xs[q * 12 + 3 + i],
                          fmaf(w2, xs[q * 12 + 4 + i],
                          fmaf(w4, xs[q * 12 + 5 + i], bias)));
                } else {
                    val = fmaf(w0, xs[q * 12 + 2 + i],
                          fmaf(w1, xs[q * 12 + 3 + i],
                          fmaf(w2, xs[q * 12 + 4 + i],
                          fmaf(w3, xs[q * 12 + 5 + i],
                          fmaf(w4, xs[q * 12 + 6 + i], bias)))));
                }
                v[i] = (!GUARDED || (pq + i < l)) ? val : 0.0f;
            }

            // BLOCK_POS and ML are multiples of 4: pq<ML implies pq+4<=ML.
            *reinterpret_cast<float4*>(rowOut + pq) =
                make_float4(v[0], v[1], v[2], v[3]);
        }
    }
}

template <int SID>
__device__ __forceinline__ void run_zero(float* __restrict__ out, int ML)
{
    const int warp = threadIdx.x >> 5;
    const int lane = threadIdx.x & 31;
    const int warpBase = blockIdx.x * BLOCK_POS + warp * WARP_POS;
    const int ch0 = blockIdx.y * CH_TILE;
    const float4 z4 = make_float4(0.f, 0.f, 0.f, 0.f);

    #pragma unroll 1
    for (int c = 0; c < CH_TILE; c++) {
        float* rowOut = out + ((size_t)(SID * D_MODEL + ch0 + c)) * (size_t)ML;
        #pragma unroll
        for (int q = 0; q < QUADS; q++) {
            const int pq = warpBase + q * 128 + lane * 4;
            if (pq < ML)
                *reinterpret_cast<float4*>(rowOut + pq) = z4;
        }
    }
}

template <int SID>
__device__ __forceinline__ void run_stream(
    const float* __restrict__ x, const float* __restrict__ W,
    const float* __restrict__ b, float* __restrict__ out,
    int l, int ML)
{
    const int base = blockIdx.x * BLOCK_POS;
    if (base >= l) {
        run_zero<SID>(out, ML);
    } else if (base >= 4 && base + BLOCK_POS + 8 <= l) {
        run_compute<SID, false>(x, W, b, out, l, ML);
    } else {
        run_compute<SID, true>(x, W, b, out, l, ML);
    }
}

__global__ __launch_bounds__(256, 5) void embed_x_kernel(
    const float* __restrict__ x0, const float* __restrict__ x1,
    const float* __restrict__ x2,
    const float* __restrict__ W, const float* __restrict__ b,
    float* __restrict__ out, int l0, int l1, int l2, int ML, int emit_s)
{
    if (blockIdx.z == 0)      run_stream<0>(x0, W, b, out, l0, ML);
    else if (blockIdx.z == 1) run_stream<1>(x1, W, b, out, l1, ML);
    else                      run_stream<2>(x2, W, b, out, l2, ML);

    // Fused S matrix: rows (first ML) then cols (next ML), ints stored exactly
    // as floats. Handled by the (y==0, z==0) block slice for its position range.
    if (emit_s && blockIdx.y == 0 && blockIdx.z == 0) {
        float* out_s = out + 3LL * D_MODEL * (long long)ML;
        const int base = blockIdx.x * BLOCK_POS;
        #pragma unroll
        for (int k = 0; k < BLOCK_POS / 256; k++) {
            const int j = base + k * 256 + threadIdx.x;
            if (j >= ML) break;
            int row, col;
            if (j < l0)                 { row = 0; col = j * 4; }
            else if (j < l0 + l1)       { row = 1; col = (j - l0) * 2; }
            else if (j < l0 + l1 + l2)  { row = 2; col = j - l0 - l1; }
            else                        { row = 0; col = 0; }
            out_s[j]      = (float)row;
            out_s[ML + j] = (float)col;
        }
    }
}

extern "C" void kernel_launch(void* const* d_in, const int* in_sizes, int n_in,
                              void* d_out, int out_size)
{
    const float* x0 = (const float*)d_in[0];  // x_250
    const float* x1 = (const float*)d_in[1];  // x_500
    const float* x2 = (const float*)d_in[2];  // x_1000
    const float* W  = (const float*)d_in[3];  // [256,1,5]
    const float* b  = (const float*)d_in[4];  // [256]

    const int l0 = in_sizes[0];
    const int l1 = in_sizes[1];
    const int l2 = in_sizes[2];
    int ML = l0;
    if (l1 > ML) ML = l1;
    if (l2 > ML) ML = l2;

    float* out = (float*)d_out;

    const long long x_elems = 3LL * D_MODEL * (long long)ML;
    const int emit_s = ((long long)out_size >= x_elems + 2LL * ML) ? 1 : 0;

    dim3 block(256, 1, 1);
    dim3 grid((ML + BLOCK_POS - 1) / BLOCK_POS, D_MODEL / CH_TILE, 3);
    embed_x_kernel<<<grid, block>>>(x0, x1, x2, W, b, out, l0, l1, l2, ML, emit_s);
}